// round 8
// baseline (speedup 1.0000x reference)
#include <cuda_runtime.h>
#include <cuda_bf16.h>
#include <cstdint>

#define NN 8192
#define DD 256
#define XSTR 259

// ---------------- device scratch ----------------
__device__ __nv_bfloat16 g_Xbf[NN * DD];      // X features bf16
__device__ __nv_bfloat16 g_Wbf[3][DD * DD];   // W bf16 [k][n] (Q folded w/ 1/16)
__device__ __nv_bfloat16 g_Qbf[NN * DD];      // Q/16 bf16
__device__ __nv_bfloat16 g_Kbf[NN * DD];
__device__ __nv_bfloat16 g_Vbf[NN * DD];
__device__ float4 g_P4[NN];                   // px,py,pz,|p|^2

// ---------------- helpers ----------------
__device__ __forceinline__ uint32_t smem_u32(const void* p) {
    uint32_t a;
    asm("{ .reg .u64 t; cvta.to.shared.u64 t, %1; cvt.u32.u64 %0, t; }" : "=r"(a) : "l"(p));
    return a;
}
__device__ __forceinline__ uint32_t pack_bf16(float lo, float hi) {
    uint32_t r;
    asm("cvt.rn.bf16x2.f32 %0, %1, %2;" : "=r"(r) : "f"(hi), "f"(lo));
    return r;
}
__device__ __forceinline__ void cp16(uint32_t s, const void* g) {
    asm volatile("cp.async.cg.shared.global [%0], [%1], 16;" :: "r"(s), "l"(g));
}
__device__ __forceinline__ void cp_commit() {
    asm volatile("cp.async.commit_group;" ::: "memory");
}
__device__ __forceinline__ void ldm4(uint32_t* r, uint32_t a) {
    asm volatile("ldmatrix.sync.aligned.m8n8.x4.shared.b16 {%0,%1,%2,%3}, [%4];"
                 : "=r"(r[0]), "=r"(r[1]), "=r"(r[2]), "=r"(r[3]) : "r"(a));
}
__device__ __forceinline__ void ldm4t(uint32_t* r, uint32_t a) {
    asm volatile("ldmatrix.sync.aligned.m8n8.x4.trans.shared.b16 {%0,%1,%2,%3}, [%4];"
                 : "=r"(r[0]), "=r"(r[1]), "=r"(r[2]), "=r"(r[3]) : "r"(a));
}
__device__ __forceinline__ void mma16816(float* c, const uint32_t* a, uint32_t b0, uint32_t b1) {
    asm volatile(
        "mma.sync.aligned.m16n8k16.row.col.f32.bf16.bf16.f32 "
        "{%0,%1,%2,%3}, {%4,%5,%6,%7}, {%8,%9}, {%0,%1,%2,%3};"
        : "+f"(c[0]), "+f"(c[1]), "+f"(c[2]), "+f"(c[3])
        : "r"(a[0]), "r"(a[1]), "r"(a[2]), "r"(a[3]), "r"(b0), "r"(b1));
}

// ---------------------------------------------------------------------------
// K0: prep — X -> bf16, positions.  (X rows only 4B-aligned: scalar loads)
// ---------------------------------------------------------------------------
__global__ __launch_bounds__(256) void prep_kernel(const float* __restrict__ X)
{
    int idx = blockIdx.x * 256 + threadIdx.x;
    int row = idx >> 5, c8 = idx & 31;
    const float* xr = X + (size_t)row * XSTR + c8 * 8;
    float v0 = xr[0], v1 = xr[1], v2 = xr[2], v3 = xr[3];
    float v4 = xr[4], v5 = xr[5], v6 = xr[6], v7 = xr[7];
    uint4 u;
    u.x = pack_bf16(v0, v1); u.y = pack_bf16(v2, v3);
    u.z = pack_bf16(v4, v5); u.w = pack_bf16(v6, v7);
    *(uint4*)&g_Xbf[(size_t)row * DD + c8 * 8] = u;
    if (c8 == 0) {
        float px = X[(size_t)row * XSTR + 256];
        float py = X[(size_t)row * XSTR + 257];
        float pz = X[(size_t)row * XSTR + 258];
        g_P4[row] = make_float4(px, py, pz, px*px + py*py + pz*pz);
    }
}

// ---------------------------------------------------------------------------
// K0b: W -> bf16 (Q folded with 1/16)
// ---------------------------------------------------------------------------
__global__ __launch_bounds__(256) void wconv_kernel(
    const float* __restrict__ WQ, const float* __restrict__ WK, const float* __restrict__ WV)
{
    int mat = blockIdx.y;
    const float* W = (mat == 0) ? WQ : (mat == 1) ? WK : WV;
    float sc = (mat == 0) ? 0.0625f : 1.0f;
    int idx = blockIdx.x * 256 + threadIdx.x;
    int base = idx * 8;
    const float4* wr = (const float4*)(W + base);
    float4 a = wr[0], b = wr[1];
    uint4 u;
    u.x = pack_bf16(a.x*sc, a.y*sc); u.y = pack_bf16(a.z*sc, a.w*sc);
    u.z = pack_bf16(b.x*sc, b.y*sc); u.w = pack_bf16(b.z*sc, b.w*sc);
    *(uint4*)&g_Wbf[mat][base] = u;
}

// ---------------------------------------------------------------------------
// K1: QKV via mma.sync.  grid (64, 3), 256 thr, warp = 16 rows x 256 cols
// ---------------------------------------------------------------------------
#define QX 0                  // 128 x 528
#define QW 67584              // 256 x 528
#define SMEMQ (67584 + 135168)

__global__ __launch_bounds__(256, 1) void qkv_mma_kernel(
    const float* __restrict__ bQ, const float* __restrict__ bK, const float* __restrict__ bV)
{
    extern __shared__ char sm[];
    const uint32_t sb = smem_u32(sm);
    const int t = threadIdx.x, lane = t & 31, w = t >> 5;
    const int g = lane >> 2, t4 = lane & 3;
    const int mat = blockIdx.y;
    const int i0 = blockIdx.x * 128;
    const float* bias = (mat == 0) ? bQ : (mat == 1) ? bK : bV;
    const float bsc = (mat == 0) ? 0.0625f : 1.0f;
    __nv_bfloat16* O = (mat == 0) ? g_Qbf : (mat == 1) ? g_Kbf : g_Vbf;

    #pragma unroll
    for (int l = 0; l < 16; l++) {
        int idx = t + l * 256;
        int r = idx >> 5, c8 = idx & 31;
        uint4 v = *(const uint4*)&g_Xbf[(size_t)(i0 + r) * DD + c8 * 8];
        *(uint4*)(sm + QX + r * 528 + c8 * 16) = v;
    }
    #pragma unroll
    for (int l = 0; l < 32; l++) {
        int idx = t + l * 256;
        int r = idx >> 5, c8 = idx & 31;
        uint4 v = *(const uint4*)&g_Wbf[mat][(size_t)r * DD + c8 * 8];
        *(uint4*)(sm + QW + r * 528 + c8 * 16) = v;
    }
    __syncthreads();

    float o[32][4];
    #pragma unroll
    for (int i = 0; i < 32; i++)
        #pragma unroll
        for (int j = 0; j < 4; j++) o[i][j] = 0.f;

    const int arow = w * 16 + (lane & 15);
    const int acol = (lane >> 4) * 8;
    const int vrow_off = ((lane >> 3) & 1) * 8 + (lane & 7);
    const int vcol_off = (lane >> 4) * 8;

    #pragma unroll
    for (int k = 0; k < 16; k++) {
        uint32_t Aa[4];
        ldm4(Aa, sb + QX + arow * 528 + (acol + k * 16) * 2);
        #pragma unroll
        for (int n16 = 0; n16 < 16; n16++) {
            uint32_t vb[4];
            ldm4t(vb, sb + QW + (k * 16 + vrow_off) * 528 + (n16 * 16 + vcol_off) * 2);
            mma16816(o[n16 * 2],     Aa, vb[0], vb[1]);
            mma16816(o[n16 * 2 + 1], Aa, vb[2], vb[3]);
        }
    }

    const int row0 = i0 + w * 16 + g;
    #pragma unroll
    for (int nb = 0; nb < 32; nb++) {
        int c = nb * 8 + t4 * 2;
        float b0 = bias[c] * bsc, b1 = bias[c + 1] * bsc;
        *(uint32_t*)&O[(size_t)row0 * DD + c]       = pack_bf16(o[nb][0] + b0, o[nb][1] + b1);
        *(uint32_t*)&O[(size_t)(row0 + 8) * DD + c] = pack_bf16(o[nb][2] + b0, o[nb][3] + b1);
    }
}

// ---------------------------------------------------------------------------
// K2: flash attention, 512 threads / 16 warps (4 per SMSP for latency hiding).
// Warp (rg, kg): S for rows rg*16..+16 x keys kg*16..+16 (of the 64-key tile).
// AV: warp (rg, dg=kg): rows rg*16..+16 x dims dg*64..+64, all 64 keys.
// Unshifted-exp softmax-one; l/m merged once at the end.
// ---------------------------------------------------------------------------
#define SQ   0                       // 64*528 = 33792
#define SK   33792                   // 2 x 33792
#define SV   101376                  // 2 x 33792
#define SP   168960                  // 64 x 144 = 9216
#define SPK  178176                  // 2 x 1024
#define SRED 180224                  // m[4][64], l[4][64] = 2048
#define SMEMB 182272

__device__ __forceinline__ void loadK(uint32_t sb, int t, int tt)
{
    if (tt < 128) {
        const int b = tt & 1;
        const int j0 = tt * 64;
        #pragma unroll
        for (int l = 0; l < 4; l++) {
            int idx = t + l * 512;
            int r = idx >> 5, c8 = idx & 31;
            cp16(sb + SK + b * 33792 + (uint32_t)(r * 528 + c8 * 16),
                 (const char*)g_Kbf + ((size_t)(j0 + r) * DD + c8 * 8) * 2);
        }
        if (t < 64) cp16(sb + SPK + b * 1024 + t * 16, &g_P4[j0 + t]);
    }
    cp_commit();
}
__device__ __forceinline__ void loadV(uint32_t sb, int t, int tt)
{
    if (tt < 128) {
        const int b = tt & 1;
        const int j0 = tt * 64;
        #pragma unroll
        for (int l = 0; l < 4; l++) {
            int idx = t + l * 512;
            int r = idx >> 5, c8 = idx & 31;
            cp16(sb + SV + b * 33792 + (uint32_t)(r * 528 + c8 * 16),
                 (const char*)g_Vbf + ((size_t)(j0 + r) * DD + c8 * 8) * 2);
        }
    }
    cp_commit();
}

__global__ __launch_bounds__(512, 1) void flash_kernel(
    const float* __restrict__ X, float* __restrict__ out)
{
    extern __shared__ char sm[];
    const uint32_t sb = smem_u32(sm);
    const int t = threadIdx.x;
    const int lane = t & 31, w = t >> 5;
    const int rg = w & 3, kg = w >> 2;         // kg = key-group (S) = dim-group (AV)
    const int g = lane >> 2, t4 = lane & 3;
    const int i0 = blockIdx.x * 64;
    const int rA = rg * 16 + g, rB = rA + 8;

    // stage Q
    #pragma unroll
    for (int l = 0; l < 4; l++) {
        int idx = t + l * 512;
        int r = idx >> 5, c8 = idx & 31;
        uint4 v = *(const uint4*)&g_Qbf[(size_t)(i0 + r) * DD + c8 * 8];
        *(uint4*)(sm + SQ + r * 528 + c8 * 16) = v;
    }
    loadK(sb, t, 0);
    loadV(sb, t, 0);
    loadK(sb, t, 1);
    loadV(sb, t, 1);

    const float4 pqA = g_P4[i0 + rA];
    const float4 pqB = g_P4[i0 + rB];

    float o[8][4];
    #pragma unroll
    for (int i = 0; i < 8; i++)
        #pragma unroll
        for (int j = 0; j < 4; j++) o[i][j] = 0.f;
    float mA = -1e30f, mB = -1e30f;   // private running max of logits
    float lA = 0.f, lB = 0.f;         // private partial sums of e^logit

    const int qrow = rg * 16 + (lane & 15);
    const int qcol = (lane >> 4) * 8;
    const int krow = kg * 16 + ((lane >> 4) << 3) + (lane & 7);
    const int kcol_off = ((lane >> 3) & 1) * 8;
    const int prow = rg * 16 + (lane & 15);
    const int pcol = (lane >> 4) * 8;
    const int vrow_off = ((lane >> 3) & 1) * 8 + (lane & 7);
    const int vcol0 = kg * 64 + (lane >> 4) * 8;

    __syncthreads();

    #pragma unroll 1
    for (int tt = 0; tt < 128; tt++) {
        const int b = tt & 1;
        asm volatile("cp.async.wait_group 2;" ::: "memory");
        __syncthreads();

        // ---- S = Q K^T (warp: 16 rows x 16 keys) ----
        const uint32_t kbase = sb + SK + b * 33792;
        float s[2][4];
        #pragma unroll
        for (int i = 0; i < 2; i++)
            #pragma unroll
            for (int j = 0; j < 4; j++) s[i][j] = 0.f;
        #pragma unroll
        for (int k = 0; k < 16; k++) {
            uint32_t Qa[4], bf[4];
            ldm4(Qa, sb + SQ + qrow * 528 + (qcol + k * 16) * 2);
            ldm4(bf, kbase + krow * 528 + (k * 16 + kcol_off) * 2);
            mma16816(s[0], Qa, bf[0], bf[1]);
            mma16816(s[1], Qa, bf[2], bf[3]);
        }

        // ---- decay, unshifted exp, private max/sum, P -> smem bf16 ----
        const float4* pk = (const float4*)(sm + SPK + b * 1024);
        #pragma unroll
        for (int nb = 0; nb < 2; nb++) {
            int c0 = kg * 16 + nb * 8 + t4 * 2;
            float4 k0 = pk[c0], k1 = pk[c0 + 1];
            float dA0 = pqA.w + k0.w - 2.f*(pqA.x*k0.x + pqA.y*k0.y + pqA.z*k0.z);
            float dA1 = pqA.w + k1.w - 2.f*(pqA.x*k1.x + pqA.y*k1.y + pqA.z*k1.z);
            float dB0 = pqB.w + k0.w - 2.f*(pqB.x*k0.x + pqB.y*k0.y + pqB.z*k0.z);
            float dB1 = pqB.w + k1.w - 2.f*(pqB.x*k1.x + pqB.y*k1.y + pqB.z*k1.z);
            float x0 = s[nb][0] * __expf(-0.5f * fmaxf(dA0, 0.f));
            float x1 = s[nb][1] * __expf(-0.5f * fmaxf(dA1, 0.f));
            float x2 = s[nb][2] * __expf(-0.5f * fmaxf(dB0, 0.f));
            float x3 = s[nb][3] * __expf(-0.5f * fmaxf(dB1, 0.f));
            mA = fmaxf(mA, fmaxf(x0, x1));
            mB = fmaxf(mB, fmaxf(x2, x3));
            float p0 = __expf(x0), p1 = __expf(x1);
            float p2 = __expf(x2), p3 = __expf(x3);
            lA += p0 + p1; lB += p2 + p3;
            *(uint32_t*)(sm + SP + rA * 144 + c0 * 2) = pack_bf16(p0, p1);
            *(uint32_t*)(sm + SP + rB * 144 + c0 * 2) = pack_bf16(p2, p3);
        }
        __syncthreads();      // P ready; K(tt), pk(tt) dead
        loadK(sb, t, tt + 2); // overlap K prefetch with AV

        // ---- O += P V (warp: 16 rows x 64 dims, all 64 keys) ----
        const uint32_t vbase = sb + SV + b * 33792;
        #pragma unroll
        for (int k = 0; k < 4; k++) {
            uint32_t Pa[4];
            ldm4(Pa, sb + SP + prow * 144 + (k * 16 + pcol) * 2);
            #pragma unroll
            for (int n16 = 0; n16 < 4; n16++) {
                uint32_t vb[4];
                ldm4t(vb, vbase + (k * 16 + vrow_off) * 528 + (vcol0 + n16 * 16) * 2);
                mma16816(o[n16 * 2],     Pa, vb[0], vb[1]);
                mma16816(o[n16 * 2 + 1], Pa, vb[2], vb[3]);
            }
        }
        __syncthreads();      // V(tt) + P free
        loadV(sb, t, tt + 2);
    }

    // ---- reduce private l/m over the quad lanes ----
    lA += __shfl_xor_sync(0xffffffffu, lA, 1);
    lA += __shfl_xor_sync(0xffffffffu, lA, 2);
    lB += __shfl_xor_sync(0xffffffffu, lB, 1);
    lB += __shfl_xor_sync(0xffffffffu, lB, 2);
    mA = fmaxf(mA, __shfl_xor_sync(0xffffffffu, mA, 1));
    mA = fmaxf(mA, __shfl_xor_sync(0xffffffffu, mA, 2));
    mB = fmaxf(mB, __shfl_xor_sync(0xffffffffu, mB, 1));
    mB = fmaxf(mB, __shfl_xor_sync(0xffffffffu, mB, 2));

    // ---- merge l/m across the 4 key-groups ----
    float* red = (float*)(sm + SRED);     // m[4][64] then l[4][64]
    if (t4 == 0) {
        red[kg * 64 + rA] = mA;       red[kg * 64 + rB] = mB;
        red[256 + kg * 64 + rA] = lA; red[256 + kg * 64 + rB] = lB;
    }
    __syncthreads();
    {
        float MA = fmaxf(fmaxf(red[rA], red[64 + rA]), fmaxf(red[128 + rA], red[192 + rA]));
        float MB = fmaxf(fmaxf(red[rB], red[64 + rB]), fmaxf(red[128 + rB], red[192 + rB]));
        float sLA = red[256 + rA] + red[320 + rA] + red[384 + rA] + red[448 + rA];
        float sLB = red[256 + rB] + red[320 + rB] + red[384 + rB] + red[448 + rB];
        float invA = 1.f / (__expf(MA) + sLA);
        float invB = 1.f / (__expf(MB) + sLB);
        const int gA = i0 + rA, gB = i0 + rB;
        #pragma unroll
        for (int nb = 0; nb < 8; nb++) {
            int c = kg * 64 + nb * 8 + t4 * 2;
            float2 vA, vB;
            vA.x = o[nb][0] * invA + X[(size_t)gA * XSTR + c];
            vA.y = o[nb][1] * invA + X[(size_t)gA * XSTR + c + 1];
            vB.x = o[nb][2] * invB + X[(size_t)gB * XSTR + c];
            vB.y = o[nb][3] * invB + X[(size_t)gB * XSTR + c + 1];
            *(float2*)&out[(size_t)gA * DD + c] = vA;
            *(float2*)&out[(size_t)gB * DD + c] = vB;
        }
    }
}

// ---------------------------------------------------------------------------
extern "C" void kernel_launch(void* const* d_in, const int* in_sizes, int n_in,
                              void* d_out, int out_size)
{
    const float* X  = (const float*)d_in[0];
    const float* WQ = (const float*)d_in[1];
    const float* bQ = (const float*)d_in[2];
    const float* WK = (const float*)d_in[3];
    const float* bK = (const float*)d_in[4];
    const float* WV = (const float*)d_in[5];
    const float* bV = (const float*)d_in[6];
    float* out = (float*)d_out;

    cudaFuncSetAttribute(flash_kernel, cudaFuncAttributeMaxDynamicSharedMemorySize, SMEMB);
    cudaFuncSetAttribute(qkv_mma_kernel, cudaFuncAttributeMaxDynamicSharedMemorySize, SMEMQ);

    prep_kernel<<<NN * 32 / 256, 256>>>(X);
    wconv_kernel<<<dim3(DD * DD / 8 / 256, 3), 256>>>(WQ, WK, WV);
    qkv_mma_kernel<<<dim3(NN / 128, 3), 256, SMEMQ>>>(bQ, bK, bV);
    flash_kernel<<<NN / 64, 512, SMEMB>>>(X, out);
}

// round 9
// speedup vs baseline: 1.2384x; 1.2384x over previous
#include <cuda_runtime.h>
#include <cuda_bf16.h>
#include <cstdint>

#define NN 8192
#define DD 256
#define XSTR 259

// ---------------- device scratch ----------------
__device__ __nv_bfloat16 g_Xbf[NN * DD];
__device__ __nv_bfloat16 g_Wbf[3][DD * DD];
__device__ __nv_bfloat16 g_Qbf[NN * DD];
__device__ __nv_bfloat16 g_Kbf[NN * DD];
__device__ __nv_bfloat16 g_Vbf[NN * DD];
__device__ float4 g_P4[NN];

// ---------------- helpers ----------------
__device__ __forceinline__ uint32_t smem_u32(const void* p) {
    uint32_t a;
    asm("{ .reg .u64 t; cvta.to.shared.u64 t, %1; cvt.u32.u64 %0, t; }" : "=r"(a) : "l"(p));
    return a;
}
__device__ __forceinline__ uint32_t pack_bf16(float lo, float hi) {
    uint32_t r;
    asm("cvt.rn.bf16x2.f32 %0, %1, %2;" : "=r"(r) : "f"(hi), "f"(lo));
    return r;
}
__device__ __forceinline__ void cp16(uint32_t s, const void* g) {
    asm volatile("cp.async.cg.shared.global [%0], [%1], 16;" :: "r"(s), "l"(g));
}
__device__ __forceinline__ void cp_commit() {
    asm volatile("cp.async.commit_group;" ::: "memory");
}
__device__ __forceinline__ void ldm4(uint32_t* r, uint32_t a) {
    asm volatile("ldmatrix.sync.aligned.m8n8.x4.shared.b16 {%0,%1,%2,%3}, [%4];"
                 : "=r"(r[0]), "=r"(r[1]), "=r"(r[2]), "=r"(r[3]) : "r"(a));
}
__device__ __forceinline__ void ldm4t(uint32_t* r, uint32_t a) {
    asm volatile("ldmatrix.sync.aligned.m8n8.x4.trans.shared.b16 {%0,%1,%2,%3}, [%4];"
                 : "=r"(r[0]), "=r"(r[1]), "=r"(r[2]), "=r"(r[3]) : "r"(a));
}
__device__ __forceinline__ void mma16816(float* c, const uint32_t* a, uint32_t b0, uint32_t b1) {
    asm volatile(
        "mma.sync.aligned.m16n8k16.row.col.f32.bf16.bf16.f32 "
        "{%0,%1,%2,%3}, {%4,%5,%6,%7}, {%8,%9}, {%0,%1,%2,%3};"
        : "+f"(c[0]), "+f"(c[1]), "+f"(c[2]), "+f"(c[3])
        : "r"(a[0]), "r"(a[1]), "r"(a[2]), "r"(a[3]), "r"(b0), "r"(b1));
}
__device__ __forceinline__ void bar_sync(int id) {
    asm volatile("bar.sync %0, 128;" :: "r"(id) : "memory");
}

// ---------------------------------------------------------------------------
// K0: prep — X -> bf16, positions (X rows only 4B-aligned: scalar loads)
// ---------------------------------------------------------------------------
__global__ __launch_bounds__(256) void prep_kernel(const float* __restrict__ X)
{
    int idx = blockIdx.x * 256 + threadIdx.x;
    int row = idx >> 5, c8 = idx & 31;
    const float* xr = X + (size_t)row * XSTR + c8 * 8;
    float v0 = xr[0], v1 = xr[1], v2 = xr[2], v3 = xr[3];
    float v4 = xr[4], v5 = xr[5], v6 = xr[6], v7 = xr[7];
    uint4 u;
    u.x = pack_bf16(v0, v1); u.y = pack_bf16(v2, v3);
    u.z = pack_bf16(v4, v5); u.w = pack_bf16(v6, v7);
    *(uint4*)&g_Xbf[(size_t)row * DD + c8 * 8] = u;
    if (c8 == 0) {
        float px = X[(size_t)row * XSTR + 256];
        float py = X[(size_t)row * XSTR + 257];
        float pz = X[(size_t)row * XSTR + 258];
        g_P4[row] = make_float4(px, py, pz, px*px + py*py + pz*pz);
    }
}

// ---------------------------------------------------------------------------
// K0b: W -> bf16 (Q folded with 1/16)
// ---------------------------------------------------------------------------
__global__ __launch_bounds__(256) void wconv_kernel(
    const float* __restrict__ WQ, const float* __restrict__ WK, const float* __restrict__ WV)
{
    int mat = blockIdx.y;
    const float* W = (mat == 0) ? WQ : (mat == 1) ? WK : WV;
    float sc = (mat == 0) ? 0.0625f : 1.0f;
    int idx = blockIdx.x * 256 + threadIdx.x;
    int base = idx * 8;
    const float4* wr = (const float4*)(W + base);
    float4 a = wr[0], b = wr[1];
    uint4 u;
    u.x = pack_bf16(a.x*sc, a.y*sc); u.y = pack_bf16(a.z*sc, a.w*sc);
    u.z = pack_bf16(b.x*sc, b.y*sc); u.w = pack_bf16(b.z*sc, b.w*sc);
    *(uint4*)&g_Wbf[mat][base] = u;
}

// ---------------------------------------------------------------------------
// K1: QKV via mma.sync.  grid (64, 3), 256 thr
// ---------------------------------------------------------------------------
#define QX 0
#define QW 67584
#define SMEMQ (67584 + 135168)

__global__ __launch_bounds__(256, 1) void qkv_mma_kernel(
    const float* __restrict__ bQ, const float* __restrict__ bK, const float* __restrict__ bV)
{
    extern __shared__ char sm[];
    const uint32_t sb = smem_u32(sm);
    const int t = threadIdx.x, lane = t & 31, w = t >> 5;
    const int g = lane >> 2, t4 = lane & 3;
    const int mat = blockIdx.y;
    const int i0 = blockIdx.x * 128;
    const float* bias = (mat == 0) ? bQ : (mat == 1) ? bK : bV;
    const float bsc = (mat == 0) ? 0.0625f : 1.0f;
    __nv_bfloat16* O = (mat == 0) ? g_Qbf : (mat == 1) ? g_Kbf : g_Vbf;

    #pragma unroll
    for (int l = 0; l < 16; l++) {
        int idx = t + l * 256;
        int r = idx >> 5, c8 = idx & 31;
        uint4 v = *(const uint4*)&g_Xbf[(size_t)(i0 + r) * DD + c8 * 8];
        *(uint4*)(sm + QX + r * 528 + c8 * 16) = v;
    }
    #pragma unroll
    for (int l = 0; l < 32; l++) {
        int idx = t + l * 256;
        int r = idx >> 5, c8 = idx & 31;
        uint4 v = *(const uint4*)&g_Wbf[mat][(size_t)r * DD + c8 * 8];
        *(uint4*)(sm + QW + r * 528 + c8 * 16) = v;
    }
    __syncthreads();

    float o[32][4];
    #pragma unroll
    for (int i = 0; i < 32; i++)
        #pragma unroll
        for (int j = 0; j < 4; j++) o[i][j] = 0.f;

    const int arow = w * 16 + (lane & 15);
    const int acol = (lane >> 4) * 8;
    const int vrow_off = ((lane >> 3) & 1) * 8 + (lane & 7);
    const int vcol_off = (lane >> 4) * 8;

    #pragma unroll
    for (int k = 0; k < 16; k++) {
        uint32_t Aa[4];
        ldm4(Aa, sb + QX + arow * 528 + (acol + k * 16) * 2);
        #pragma unroll
        for (int n16 = 0; n16 < 16; n16++) {
            uint32_t vb[4];
            ldm4t(vb, sb + QW + (k * 16 + vrow_off) * 528 + (n16 * 16 + vcol_off) * 2);
            mma16816(o[n16 * 2],     Aa, vb[0], vb[1]);
            mma16816(o[n16 * 2 + 1], Aa, vb[2], vb[3]);
        }
    }

    const int row0 = i0 + w * 16 + g;
    #pragma unroll
    for (int nb = 0; nb < 32; nb++) {
        int c = nb * 8 + t4 * 2;
        float b0 = bias[c] * bsc, b1 = bias[c + 1] * bsc;
        *(uint32_t*)&O[(size_t)row0 * DD + c]       = pack_bf16(o[nb][0] + b0, o[nb][1] + b1);
        *(uint32_t*)&O[(size_t)(row0 + 8) * DD + c] = pack_bf16(o[nb][2] + b0, o[nb][3] + b1);
    }
}

// ---------------------------------------------------------------------------
// K2: flash attention, PING-PONG warp groups.
// 256 threads = 2 groups x 4 warps.  Group g handles tiles g, g+2, ... with
// its own K/V buffers + named barrier -> groups run phase-shifted, keeping
// the tensor pipe busy while the other group does exp/barriers/loads.
// Warp (group, rg): rows rg*16..+16, all 64 keys of the group's tile.
// P register-resident (C-layout == A-layout).  Unshifted-exp softmax-one.
// ---------------------------------------------------------------------------
#define SQ    0                      // 64*528 = 33792
#define SKB   33792                  // 2 group bufs x 33792
#define SVB   101376                 // 2 group bufs x 33792
#define SPKB  168960                 // 2 x 1024
#define SRED  171008                 // m[2][64], l[2][64] = 1024
#define SMEMB 172032
// epilogue oM f32[64][256] reuses sm[0 .. 65536]

__device__ __forceinline__ void loadK(uint32_t sb, int tg, int g, int tt)
{
    if (tt < 128) {
        const int j0 = tt * 64;
        #pragma unroll
        for (int l = 0; l < 16; l++) {
            int idx = tg + l * 128;
            int r = idx >> 5, c8 = idx & 31;
            cp16(sb + SKB + g * 33792 + (uint32_t)(r * 528 + c8 * 16),
                 (const char*)g_Kbf + ((size_t)(j0 + r) * DD + c8 * 8) * 2);
        }
        if (tg < 64) cp16(sb + SPKB + g * 1024 + tg * 16, &g_P4[j0 + tg]);
    }
    cp_commit();
}
__device__ __forceinline__ void loadV(uint32_t sb, int tg, int g, int tt)
{
    if (tt < 128) {
        const int j0 = tt * 64;
        #pragma unroll
        for (int l = 0; l < 16; l++) {
            int idx = tg + l * 128;
            int r = idx >> 5, c8 = idx & 31;
            cp16(sb + SVB + g * 33792 + (uint32_t)(r * 528 + c8 * 16),
                 (const char*)g_Vbf + ((size_t)(j0 + r) * DD + c8 * 8) * 2);
        }
    }
    cp_commit();
}

__global__ __launch_bounds__(256, 1) void flash_kernel(
    const float* __restrict__ X, float* __restrict__ out)
{
    extern __shared__ char sm[];
    const uint32_t sb = smem_u32(sm);
    const int t = threadIdx.x;
    const int lane = t & 31, w = t >> 5;
    const int rg = w & 3, g = w >> 2;       // group g = 0/1
    const int tg = t & 127;
    const int lg = lane >> 2, t4 = lane & 3;
    const int i0 = blockIdx.x * 64;
    const int rA = rg * 16 + lg, rB = rA + 8;
    const int barid = 1 + g;

    // stage Q (all threads)
    #pragma unroll
    for (int l = 0; l < 8; l++) {
        int idx = t + l * 256;
        int r = idx >> 5, c8 = idx & 31;
        uint4 v = *(const uint4*)&g_Qbf[(size_t)(i0 + r) * DD + c8 * 8];
        *(uint4*)(sm + SQ + r * 528 + c8 * 16) = v;
    }
    // group-private initial loads: K(g) then V(g)
    loadK(sb, tg, g, g);
    loadV(sb, tg, g, g);

    const float4 pqA = g_P4[i0 + rA];
    const float4 pqB = g_P4[i0 + rB];
    __syncthreads();   // Q visible to all

    float o[32][4];
    #pragma unroll
    for (int i = 0; i < 32; i++)
        #pragma unroll
        for (int j = 0; j < 4; j++) o[i][j] = 0.f;
    float mA = -1e30f, mB = -1e30f;
    float lA = 0.f, lB = 0.f;

    const int qrow = rg * 16 + (lane & 15);
    const int qcol = (lane >> 4) * 8;
    const int krow_off = ((lane >> 4) << 3) + (lane & 7);
    const int kcol_off = ((lane >> 3) & 1) * 8;
    const int vrow_off = ((lane >> 3) & 1) * 8 + (lane & 7);
    const int vcol_off = (lane >> 4) * 8;
    const uint32_t kbase = sb + SKB + g * 33792;
    const uint32_t vbase = sb + SVB + g * 33792;

    #pragma unroll 1
    for (int tt = g; tt < 128; tt += 2) {
        // K(tt) ready (V(tt) may still be in flight)
        asm volatile("cp.async.wait_group 1;" ::: "memory");
        bar_sync(barid);

        // ---- S = Q K^T : 16 rows x 64 keys ----
        float s[8][4];
        #pragma unroll
        for (int i = 0; i < 8; i++)
            #pragma unroll
            for (int j = 0; j < 4; j++) s[i][j] = 0.f;
        #pragma unroll
        for (int k = 0; k < 16; k++) {
            uint32_t Qa[4];
            ldm4(Qa, sb + SQ + qrow * 528 + (qcol + k * 16) * 2);
            #pragma unroll
            for (int np = 0; np < 4; np++) {
                uint32_t bf[4];
                ldm4(bf, kbase + (np * 16 + krow_off) * 528 + (k * 16 + kcol_off) * 2);
                mma16816(s[np * 2],     Qa, bf[0], bf[1]);
                mma16816(s[np * 2 + 1], Qa, bf[2], bf[3]);
            }
        }

        // ---- decay + unshifted exp -> register P (A-frag layout) ----
        const float4* pk = (const float4*)(sm + SPKB + g * 1024);
        uint32_t aa[4][4];
        #pragma unroll
        for (int nb = 0; nb < 8; nb++) {
            int c0 = nb * 8 + t4 * 2;
            float4 k0 = pk[c0], k1 = pk[c0 + 1];
            float dA0 = pqA.w + k0.w - 2.f*(pqA.x*k0.x + pqA.y*k0.y + pqA.z*k0.z);
            float dA1 = pqA.w + k1.w - 2.f*(pqA.x*k1.x + pqA.y*k1.y + pqA.z*k1.z);
            float dB0 = pqB.w + k0.w - 2.f*(pqB.x*k0.x + pqB.y*k0.y + pqB.z*k0.z);
            float dB1 = pqB.w + k1.w - 2.f*(pqB.x*k1.x + pqB.y*k1.y + pqB.z*k1.z);
            float x0 = s[nb][0] * __expf(-0.5f * fmaxf(dA0, 0.f));
            float x1 = s[nb][1] * __expf(-0.5f * fmaxf(dA1, 0.f));
            float x2 = s[nb][2] * __expf(-0.5f * fmaxf(dB0, 0.f));
            float x3 = s[nb][3] * __expf(-0.5f * fmaxf(dB1, 0.f));
            mA = fmaxf(mA, fmaxf(x0, x1));
            mB = fmaxf(mB, fmaxf(x2, x3));
            float p0 = __expf(x0), p1 = __expf(x1);
            float p2 = __expf(x2), p3 = __expf(x3);
            lA += p0 + p1; lB += p2 + p3;
            if ((nb & 1) == 0) {
                aa[nb >> 1][0] = pack_bf16(p0, p1);
                aa[nb >> 1][1] = pack_bf16(p2, p3);
            } else {
                aa[nb >> 1][2] = pack_bf16(p0, p1);
                aa[nb >> 1][3] = pack_bf16(p2, p3);
            }
        }

        // V(tt) present to all + K consumed by all -> refill K
        asm volatile("cp.async.wait_group 0;" ::: "memory");
        bar_sync(barid);
        loadK(sb, tg, g, tt + 2);

        // ---- O += P V : 16 rows x 256 dims, 64 keys ----
        #pragma unroll
        for (int ks = 0; ks < 4; ks++) {
            #pragma unroll
            for (int n16 = 0; n16 < 16; n16++) {
                uint32_t vb[4];
                ldm4t(vb, vbase + (ks * 16 + vrow_off) * 528 + (n16 * 16 + vcol_off) * 2);
                mma16816(o[n16 * 2],     aa[ks], vb[0], vb[1]);
                mma16816(o[n16 * 2 + 1], aa[ks], vb[2], vb[3]);
            }
        }
        bar_sync(barid);       // V consumed by all -> refill V
        loadV(sb, tg, g, tt + 2);
    }

    // ---- reduce private l/m over quad lanes ----
    lA += __shfl_xor_sync(0xffffffffu, lA, 1);
    lA += __shfl_xor_sync(0xffffffffu, lA, 2);
    lB += __shfl_xor_sync(0xffffffffu, lB, 1);
    lB += __shfl_xor_sync(0xffffffffu, lB, 2);
    mA = fmaxf(mA, __shfl_xor_sync(0xffffffffu, mA, 1));
    mA = fmaxf(mA, __shfl_xor_sync(0xffffffffu, mA, 2));
    mB = fmaxf(mB, __shfl_xor_sync(0xffffffffu, mB, 1));
    mB = fmaxf(mB, __shfl_xor_sync(0xffffffffu, mB, 2));

    float* red = (float*)(sm + SRED);    // m[2][64] then l[2][64]
    if (t4 == 0) {
        red[g * 64 + rA] = mA;       red[g * 64 + rB] = mB;
        red[128 + g * 64 + rA] = lA; red[128 + g * 64 + rB] = lB;
    }
    __syncthreads();     // both groups done computing; buffers now dead

    // ---- merge group outputs ----
    float* oM = (float*)sm;              // [64][256] f32, reuses SQ/K0 area
    if (g == 1) {
        #pragma unroll
        for (int nb = 0; nb < 32; nb++) {
            int c = nb * 8 + t4 * 2;
            oM[rA * 256 + c] = o[nb][0]; oM[rA * 256 + c + 1] = o[nb][1];
            oM[rB * 256 + c] = o[nb][2]; oM[rB * 256 + c + 1] = o[nb][3];
        }
    }
    __syncthreads();
    if (g == 0) {
        float MA = fmaxf(red[rA], red[64 + rA]);
        float MB = fmaxf(red[rB], red[64 + rB]);
        float invA = 1.f / (__expf(MA) + red[128 + rA] + red[192 + rA]);
        float invB = 1.f / (__expf(MB) + red[128 + rB] + red[192 + rB]);
        const int gA = i0 + rA, gB = i0 + rB;
        #pragma unroll
        for (int nb = 0; nb < 32; nb++) {
            int c = nb * 8 + t4 * 2;
            float2 vA, vB;
            vA.x = (o[nb][0] + oM[rA * 256 + c])     * invA + X[(size_t)gA * XSTR + c];
            vA.y = (o[nb][1] + oM[rA * 256 + c + 1]) * invA + X[(size_t)gA * XSTR + c + 1];
            vB.x = (o[nb][2] + oM[rB * 256 + c])     * invB + X[(size_t)gB * XSTR + c];
            vB.y = (o[nb][3] + oM[rB * 256 + c + 1]) * invB + X[(size_t)gB * XSTR + c + 1];
            *(float2*)&out[(size_t)gA * DD + c] = vA;
            *(float2*)&out[(size_t)gB * DD + c] = vB;
        }
    }
}

// ---------------------------------------------------------------------------
extern "C" void kernel_launch(void* const* d_in, const int* in_sizes, int n_in,
                              void* d_out, int out_size)
{
    const float* X  = (const float*)d_in[0];
    const float* WQ = (const float*)d_in[1];
    const float* bQ = (const float*)d_in[2];
    const float* WK = (const float*)d_in[3];
    const float* bK = (const float*)d_in[4];
    const float* WV = (const float*)d_in[5];
    const float* bV = (const float*)d_in[6];
    float* out = (float*)d_out;

    cudaFuncSetAttribute(flash_kernel, cudaFuncAttributeMaxDynamicSharedMemorySize, SMEMB);
    cudaFuncSetAttribute(qkv_mma_kernel, cudaFuncAttributeMaxDynamicSharedMemorySize, SMEMQ);

    prep_kernel<<<NN * 32 / 256, 256>>>(X);
    wconv_kernel<<<dim3(DD * DD / 8 / 256, 3), 256>>>(WQ, WK, WV);
    qkv_mma_kernel<<<dim3(NN / 128, 3), 256, SMEMQ>>>(bQ, bK, bV);
    flash_kernel<<<NN / 64, 256, SMEMB>>>(X, out);
}